// round 4
// baseline (speedup 1.0000x reference)
#include <cuda_runtime.h>
#include <math.h>

#define BSZ 4
#define NN 256
#define DXD 256
#define DFFD 1024
#define EPSV 1e-5f
#define MROWS (BSZ*NN)   // 1024

// ---------------- scratch (allocation-free) ----------------
__device__ float g_Q   [MROWS*DXD];
__device__ float g_K   [MROWS*DXD];
__device__ float g_V   [MROWS*DXD];
__device__ float g_att [MROWS*DXD];
__device__ float g_proj[MROWS*DXD];
__device__ float g_X1  [MROWS*DXD];
__device__ float g_ffn1[MROWS*DFFD];
__device__ float g_ffn2[MROWS*DXD];

__device__ __forceinline__ float* scratch_ptr(int id) {
    switch (id) {
        case 0: return g_Q;
        case 1: return g_K;
        case 2: return g_V;
        case 3: return g_att;
        case 4: return g_proj;
        case 5: return g_X1;
        case 6: return g_ffn1;
        default: return g_ffn2;
    }
}

// ---------------- tf32 helpers ----------------
__device__ __forceinline__ float f2tf32(float x) {
    unsigned r;
    asm("cvt.rna.tf32.f32 %0, %1;" : "=r"(r) : "f"(x));
    return __uint_as_float(r);
}

__device__ __forceinline__ void mma_tf32(float& c0, float& c1, float& c2, float& c3,
                                         unsigned a0, unsigned a1, unsigned a2, unsigned a3,
                                         unsigned b0, unsigned b1)
{
    asm volatile(
        "mma.sync.aligned.m16n8k8.row.col.f32.tf32.tf32.f32 "
        "{%0,%1,%2,%3}, {%4,%5,%6,%7}, {%8,%9}, {%0,%1,%2,%3};"
        : "+f"(c0), "+f"(c1), "+f"(c2), "+f"(c3)
        : "r"(a0), "r"(a1), "r"(a2), "r"(a3), "r"(b0), "r"(b1));
}

// ---------------- tf32 tensor-core GEMM, register-prefetch pipelined ----------------
// BM = MT*32, BN = 64, BK = 32, 256 threads = 8 warps in 2(M) x 4(N) layout.
#define SA 36   // As row stride (BK=32 + 4 pad)
#define SB 68   // Bs row stride (BN=64 + 4 pad)

template<int MT, int K>
__device__ __forceinline__ void tgemm_core(const float* __restrict__ A,
                                           const float* __restrict__ W,
                                           const float* __restrict__ bias,
                                           float* __restrict__ Out,
                                           int N, int act,
                                           const float* __restrict__ rowmask,
                                           int row0, int col0)
{
    constexpr int BM  = MT * 32;
    constexpr int AIT = BM * 32 / 1024;   // float4 A-loads per thread (1 or 2)
    __shared__ float As[BM][SA];
    __shared__ float Bs[32][SB];

    const int tid    = threadIdx.x;
    const int lane   = tid & 31;
    const int wid    = tid >> 5;
    const int warp_m = wid & 1;
    const int warp_n = wid >> 1;
    const int lr = lane >> 2;
    const int lc = lane & 3;

    // per-thread load coords
    const int am[2] = { (tid + 0)   >> 3, (tid + 256) >> 3 };
    const int aq    = tid & 7;
    const int bk0   = tid >> 4;
    const int bq    = tid & 15;

    float4 ra[AIT], rb[2];

    // prefetch k-tile 0
#pragma unroll
    for (int it = 0; it < AIT; it++)
        ra[it] = *(const float4*)&A[(size_t)(row0 + am[it]) * K + aq * 4];
    rb[0] = *(const float4*)&W[(size_t)(bk0)      * N + col0 + bq * 4];
    rb[1] = *(const float4*)&W[(size_t)(bk0 + 16) * N + col0 + bq * 4];

    float acc[MT][2][4];
#pragma unroll
    for (int mt = 0; mt < MT; mt++)
#pragma unroll
        for (int nt = 0; nt < 2; nt++)
#pragma unroll
            for (int i = 0; i < 4; i++) acc[mt][nt][i] = 0.f;

#pragma unroll
    for (int kt = 0; kt < K; kt += 32) {
        // commit prefetched tile to smem (with tf32 rounding)
#pragma unroll
        for (int it = 0; it < AIT; it++) {
            As[am[it]][aq * 4 + 0] = f2tf32(ra[it].x);
            As[am[it]][aq * 4 + 1] = f2tf32(ra[it].y);
            As[am[it]][aq * 4 + 2] = f2tf32(ra[it].z);
            As[am[it]][aq * 4 + 3] = f2tf32(ra[it].w);
        }
#pragma unroll
        for (int it = 0; it < 2; it++) {
            Bs[bk0 + it * 16][bq * 4 + 0] = f2tf32(it ? rb[1].x : rb[0].x);
            Bs[bk0 + it * 16][bq * 4 + 1] = f2tf32(it ? rb[1].y : rb[0].y);
            Bs[bk0 + it * 16][bq * 4 + 2] = f2tf32(it ? rb[1].z : rb[0].z);
            Bs[bk0 + it * 16][bq * 4 + 3] = f2tf32(it ? rb[1].w : rb[0].w);
        }
        __syncthreads();

        // prefetch next tile (LDGs overlap the mma work below)
        if (kt + 32 < K) {
#pragma unroll
            for (int it = 0; it < AIT; it++)
                ra[it] = *(const float4*)&A[(size_t)(row0 + am[it]) * K + kt + 32 + aq * 4];
            rb[0] = *(const float4*)&W[(size_t)(kt + 32 + bk0)      * N + col0 + bq * 4];
            rb[1] = *(const float4*)&W[(size_t)(kt + 32 + bk0 + 16) * N + col0 + bq * 4];
        }

#pragma unroll
        for (int ks = 0; ks < 4; ks++) {
            const int k0 = ks * 8;
            unsigned b0[2], b1[2];
#pragma unroll
            for (int nt = 0; nt < 2; nt++) {
                const float* pb = &Bs[k0 + lc][warp_n * 16 + nt * 8 + lr];
                b0[nt] = __float_as_uint(pb[0]);
                b1[nt] = __float_as_uint(pb[4 * SB]);
            }
#pragma unroll
            for (int mt = 0; mt < MT; mt++) {
                const float* pa = &As[warp_m * (BM / 2) + mt * 16 + lr][k0 + lc];
                unsigned a0 = __float_as_uint(pa[0]);
                unsigned a1 = __float_as_uint(pa[8 * SA]);
                unsigned a2 = __float_as_uint(pa[4]);
                unsigned a3 = __float_as_uint(pa[8 * SA + 4]);
#pragma unroll
                for (int nt = 0; nt < 2; nt++)
                    mma_tf32(acc[mt][nt][0], acc[mt][nt][1], acc[mt][nt][2], acc[mt][nt][3],
                             a0, a1, a2, a3, b0[nt], b1[nt]);
            }
        }
        __syncthreads();
    }

    // epilogue
#pragma unroll
    for (int mt = 0; mt < MT; mt++) {
#pragma unroll
        for (int nt = 0; nt < 2; nt++) {
            const int col = col0 + warp_n * 16 + nt * 8 + 2 * lc;
            const float bv0 = bias[col], bv1 = bias[col + 1];
#pragma unroll
            for (int h = 0; h < 2; h++) {
                const int row = row0 + warp_m * (BM / 2) + mt * 16 + lr + h * 8;
                const float rm = rowmask ? rowmask[row] : 1.f;
                float v0 = acc[mt][nt][2 * h + 0] + bv0;
                float v1 = acc[mt][nt][2 * h + 1] + bv1;
                if (act) { v0 = fmaxf(v0, 0.f); v1 = fmaxf(v1, 0.f); }
                Out[(size_t)row * N + col]     = v0 * rm;
                Out[(size_t)row * N + col + 1] = v1 * rm;
            }
        }
    }
}

template<int MT, int K>
__global__ __launch_bounds__(256)
void tgemm_kernel(const float* __restrict__ Aext, int Aid,
                  const float* __restrict__ W,
                  const float* __restrict__ bias,
                  float* __restrict__ Oext, int Oid,
                  int N, int act,
                  const float* __restrict__ rowmask)
{
    const float* A = Aext ? Aext : scratch_ptr(Aid);
    float* Out = Oext ? Oext : scratch_ptr(Oid);
    tgemm_core<MT, K>(A, W, bias, Out, N, act, rowmask,
                      blockIdx.y * MT * 32, blockIdx.x * 64);
}

// fused Q/K/V projections: blockIdx.z selects weight set + destination
__global__ __launch_bounds__(256)
void qkv_kernel(const float* __restrict__ X,
                const float* __restrict__ Wq, const float* __restrict__ bq,
                const float* __restrict__ Wk, const float* __restrict__ bk,
                const float* __restrict__ Wv, const float* __restrict__ bv,
                const float* __restrict__ rowmask)
{
    const float* W; const float* b; float* Out;
    if (blockIdx.z == 0)      { W = Wq; b = bq; Out = g_Q; }
    else if (blockIdx.z == 1) { W = Wk; b = bk; Out = g_K; }
    else                      { W = Wv; b = bv; Out = g_V; }
    tgemm_core<2, DXD>(X, W, b, Out, DXD, 0, rowmask,
                       blockIdx.y * 64, blockIdx.x * 64);
}

// ---------------- attention: float4, 4-way j-parallel, per-channel softmax ----------------
__global__ __launch_bounds__(256)
void attn_kernel(const float* __restrict__ e_add,
                 const float* __restrict__ e_mul,
                 const float* __restrict__ y_x_add,
                 const float* __restrict__ y_x_mul,
                 const float* __restrict__ node_mask)
{
    const int bi  = blockIdx.x;          // b*N + i
    const int b   = bi >> 8;
    const int tid = threadIdx.x;
    const int jg  = tid >> 6;            // 0..3
    const int c0  = (tid & 63) * 4;      // channel quad base

    __shared__ float sm_ee[NN];          // mask_i * mask_j
    __shared__ float sm_on[NN];          // 1/0 gate
    __shared__ float red_s[4][NN];
    __shared__ float red_a[4][NN];

    if (tid < NN) {
        const float mj = node_mask[b * NN + tid];
        const float mi = node_mask[b * NN + (bi & (NN - 1))];
        sm_ee[tid] = mi * mj;
        sm_on[tid] = (mj > 0.f) ? 1.f : 0.f;
    }
    __syncthreads();

    const float inv_sqrt_df = 0.1767766952966369f;

    float4 q = *(const float4*)&g_Q[(size_t)bi * DXD + c0];
    q.x *= inv_sqrt_df; q.y *= inv_sqrt_df; q.z *= inv_sqrt_df; q.w *= inv_sqrt_df;

    const float* __restrict__ pem = e_mul + (size_t)bi * NN * DXD + c0;
    const float* __restrict__ pea = e_add + (size_t)bi * NN * DXD + c0;
    const float* __restrict__ pk  = g_K   + (size_t)b  * NN * DXD + c0;
    const float* __restrict__ pv  = g_V   + (size_t)b  * NN * DXD + c0;

    float4 s   = make_float4(0.f, 0.f, 0.f, 0.f);
    float4 acc = make_float4(0.f, 0.f, 0.f, 0.f);

#pragma unroll 4
    for (int j = jg; j < NN; j += 4) {
        const float ee = sm_ee[j];
        const float on = sm_on[j];
        const size_t off = (size_t)j * DXD;
        const float4 em = *(const float4*)(pem + off);
        const float4 ea = *(const float4*)(pea + off);
        const float4 kk = *(const float4*)(pk  + off);
        const float4 vv = *(const float4*)(pv  + off);

        float y, p;
        y = fmaf(q.x * kk.x, fmaf(em.x, ee, 1.f), ea.x * ee);
        p = on * __expf(y);  s.x += p;  acc.x = fmaf(p, vv.x, acc.x);
        y = fmaf(q.y * kk.y, fmaf(em.y, ee, 1.f), ea.y * ee);
        p = on * __expf(y);  s.y += p;  acc.y = fmaf(p, vv.y, acc.y);
        y = fmaf(q.z * kk.z, fmaf(em.z, ee, 1.f), ea.z * ee);
        p = on * __expf(y);  s.z += p;  acc.z = fmaf(p, vv.z, acc.z);
        y = fmaf(q.w * kk.w, fmaf(em.w, ee, 1.f), ea.w * ee);
        p = on * __expf(y);  s.w += p;  acc.w = fmaf(p, vv.w, acc.w);
    }

    *(float4*)&red_s[jg][c0] = s;
    *(float4*)&red_a[jg][c0] = acc;
    __syncthreads();

    if (jg == 0) {
        float4 s0 = *(float4*)&red_s[0][c0];
        float4 s1 = *(float4*)&red_s[1][c0];
        float4 s2 = *(float4*)&red_s[2][c0];
        float4 s3 = *(float4*)&red_s[3][c0];
        float4 a0 = *(float4*)&red_a[0][c0];
        float4 a1 = *(float4*)&red_a[1][c0];
        float4 a2 = *(float4*)&red_a[2][c0];
        float4 a3 = *(float4*)&red_a[3][c0];

        const float4 ya = *(const float4*)&y_x_add[b * DXD + c0];
        const float4 ym = *(const float4*)&y_x_mul[b * DXD + c0];

        float4 o;
        o.x = ya.x + (ym.x + 1.f) * ((a0.x + a1.x + a2.x + a3.x) / (s0.x + s1.x + s2.x + s3.x));
        o.y = ya.y + (ym.y + 1.f) * ((a0.y + a1.y + a2.y + a3.y) / (s0.y + s1.y + s2.y + s3.y));
        o.z = ya.z + (ym.z + 1.f) * ((a0.z + a1.z + a2.z + a3.z) / (s0.z + s1.z + s2.z + s3.z));
        o.w = ya.w + (ym.w + 1.f) * ((a0.w + a1.w + a2.w + a3.w) / (s0.w + s1.w + s2.w + s3.w));
        *(float4*)&g_att[(size_t)bi * DXD + c0] = o;
    }
}

// ---------------- single-pass layer norm over last dim (256) ----------------
__global__ __launch_bounds__(256)
void ln_kernel(const float* __restrict__ Aext, int Aid,
               const float* __restrict__ Bext, int Bid,
               const float* __restrict__ g, const float* __restrict__ beta,
               float* __restrict__ Oext, int Oid)
{
    const float* A = Aext ? Aext : scratch_ptr(Aid);
    const float* B = Bext ? Bext : scratch_ptr(Bid);
    float* Out = Oext ? Oext : scratch_ptr(Oid);

    __shared__ float red[16];

    const int row = blockIdx.x;
    const int t   = threadIdx.x;

    const float x = A[(size_t)row * DXD + t] + B[(size_t)row * DXD + t];
    float sx = x, sxx = x * x;
#pragma unroll
    for (int o = 16; o; o >>= 1) {
        sx  += __shfl_xor_sync(0xffffffffu, sx,  o);
        sxx += __shfl_xor_sync(0xffffffffu, sxx, o);
    }
    if ((t & 31) == 0) { red[t >> 5] = sx; red[8 + (t >> 5)] = sxx; }
    __syncthreads();
    sx  = red[0] + red[1] + red[2]  + red[3]  + red[4]  + red[5]  + red[6]  + red[7];
    sxx = red[8] + red[9] + red[10] + red[11] + red[12] + red[13] + red[14] + red[15];

    const float mu  = sx * (1.f / DXD);
    const float var = sxx * (1.f / DXD) - mu * mu;
    Out[(size_t)row * DXD + t] = (x - mu) * rsqrtf(var + EPSV) * g[t] + beta[t];
}

// ---------------- launch ----------------
extern "C" void kernel_launch(void* const* d_in, const int* in_sizes, int n_in,
                              void* d_out, int out_size)
{
    const float* X      = (const float*)d_in[0];
    const float* e_add  = (const float*)d_in[1];
    const float* e_mul  = (const float*)d_in[2];
    const float* yxa    = (const float*)d_in[3];
    const float* yxm    = (const float*)d_in[4];
    const float* nmask  = (const float*)d_in[5];
    const float* Wq     = (const float*)d_in[6];
    const float* bq     = (const float*)d_in[7];
    const float* Wk     = (const float*)d_in[8];
    const float* bk     = (const float*)d_in[9];
    const float* Wv     = (const float*)d_in[10];
    const float* bv     = (const float*)d_in[11];
    const float* Wo     = (const float*)d_in[12];
    const float* bo     = (const float*)d_in[13];
    const float* W1     = (const float*)d_in[14];
    const float* b1     = (const float*)d_in[15];
    const float* W2     = (const float*)d_in[16];
    const float* b2     = (const float*)d_in[17];
    const float* g1     = (const float*)d_in[18];
    const float* beta1  = (const float*)d_in[19];
    const float* g2     = (const float*)d_in[20];
    const float* b2ln   = (const float*)d_in[21];
    float* out          = (float*)d_out;

    // fused QKV (tf32): 192 blocks
    qkv_kernel<<<dim3(DXD / 64, MROWS / 64, 3), 256>>>(X, Wq, bq, Wk, bk, Wv, bv, nmask);

    // edge-modulated per-channel attention
    attn_kernel<<<MROWS, 256>>>(e_add, e_mul, yxa, yxm, nmask);

    // output projection (masked): BM=32 -> 128 blocks
    tgemm_kernel<1, DXD><<<dim3(DXD / 64, MROWS / 32), 256>>>(nullptr, 3, Wo, bo, nullptr, 4,
                                                              DXD, 0, nmask);

    // LN1: X1 = LN(X + proj)
    ln_kernel<<<MROWS, 256>>>(X, -1, nullptr, 4, g1, beta1, nullptr, 5);

    // FFN1: relu(X1 @ W1 + b1): 256 blocks
    tgemm_kernel<2, DXD><<<dim3(DFFD / 64, MROWS / 64), 256>>>(nullptr, 5, W1, b1, nullptr, 6,
                                                               DFFD, 1, nullptr);

    // FFN2: BM=32 -> 128 blocks, K=1024
    tgemm_kernel<1, DFFD><<<dim3(DXD / 64, MROWS / 32), 256>>>(nullptr, 6, W2, b2, nullptr, 7,
                                                               DXD, 0, nullptr);

    // LN2 -> out
    ln_kernel<<<MROWS, 256>>>(nullptr, 5, nullptr, 7, g2, b2ln, out, -1);
}

// round 7
// speedup vs baseline: 1.0509x; 1.0509x over previous
#include <cuda_runtime.h>
#include <math.h>

#define BSZ 4
#define NN 256
#define DXD 256
#define DFFD 1024
#define EPSV 1e-5f
#define MROWS (BSZ*NN)   // 1024

// ---------------- scratch (allocation-free) ----------------
__device__ __align__(16) float g_Q   [MROWS*DXD];
__device__ __align__(16) float g_K   [MROWS*DXD];
__device__ __align__(16) float g_V   [MROWS*DXD];
__device__ __align__(16) float g_att [MROWS*DXD];   // tf32-rounded
__device__ __align__(16) float g_proj[MROWS*DXD];
__device__ __align__(16) float g_X1  [MROWS*DXD];
__device__ __align__(16) float g_ffn1[MROWS*DFFD];  // tf32-rounded
__device__ __align__(16) float g_ffn2[MROWS*DXD];
__device__ __align__(16) float g_Xt  [MROWS*DXD];   // tf32-rounded inputs/weights
__device__ __align__(16) float g_Wqt [DXD*DXD];
__device__ __align__(16) float g_Wkt [DXD*DXD];
__device__ __align__(16) float g_Wvt [DXD*DXD];
__device__ __align__(16) float g_Wot [DXD*DXD];
__device__ __align__(16) float g_W1t [DXD*DFFD];
__device__ __align__(16) float g_W2t [DFFD*DXD];
__device__ __align__(16) float g_X1t [MROWS*DXD];

__device__ __forceinline__ float* scratch_ptr(int id) {
    switch (id) {
        case 0: return g_Q;
        case 1: return g_K;
        case 2: return g_V;
        case 3: return g_att;
        case 4: return g_proj;
        case 5: return g_X1;
        case 6: return g_ffn1;
        case 7: return g_ffn2;
        case 8: return g_Xt;
        case 9: return g_Wqt;
        case 10: return g_Wkt;
        case 11: return g_Wvt;
        case 12: return g_Wot;
        case 13: return g_W1t;
        case 14: return g_W2t;
        default: return g_X1t;
    }
}

// ---------------- tf32 / cp.async helpers ----------------
__device__ __forceinline__ float f2tf32(float x) {
    unsigned r;
    asm("cvt.rna.tf32.f32 %0, %1;" : "=r"(r) : "f"(x));
    return __uint_as_float(r);
}

__device__ __forceinline__ void cp_async16(unsigned saddr, const void* gptr) {
    asm volatile("cp.async.ca.shared.global [%0], [%1], 16;" :: "r"(saddr), "l"(gptr));
}
#define CP_COMMIT() asm volatile("cp.async.commit_group;" ::: "memory")
#define CP_WAIT(n)  asm volatile("cp.async.wait_group %0;" :: "n"(n) : "memory")

__device__ __forceinline__ void mma_tf32(float& c0, float& c1, float& c2, float& c3,
                                         unsigned a0, unsigned a1, unsigned a2, unsigned a3,
                                         unsigned b0, unsigned b1)
{
    asm volatile(
        "mma.sync.aligned.m16n8k8.row.col.f32.tf32.tf32.f32 "
        "{%0,%1,%2,%3}, {%4,%5,%6,%7}, {%8,%9}, {%0,%1,%2,%3};"
        : "+f"(c0), "+f"(c1), "+f"(c2), "+f"(c3)
        : "r"(a0), "r"(a1), "r"(a2), "r"(a3), "r"(b0), "r"(b1));
}

// ---------------- prep: round X + all weights to tf32 once ----------------
__global__ __launch_bounds__(256)
void prep_kernel(const float* __restrict__ X,
                 const float* __restrict__ Wq, const float* __restrict__ Wk,
                 const float* __restrict__ Wv, const float* __restrict__ Wo,
                 const float* __restrict__ W1, const float* __restrict__ W2)
{
    const int idx = blockIdx.x * 256 + threadIdx.x;   // 0 .. 1048575
    const float* src; float* dst; int off;
    if      (idx <  262144) { src = X;  dst = g_Xt;  off = idx; }
    else if (idx <  327680) { src = Wq; dst = g_Wqt; off = idx -  262144; }
    else if (idx <  393216) { src = Wk; dst = g_Wkt; off = idx -  327680; }
    else if (idx <  458752) { src = Wv; dst = g_Wvt; off = idx -  393216; }
    else if (idx <  524288) { src = Wo; dst = g_Wot; off = idx -  458752; }
    else if (idx <  786432) { src = W1; dst = g_W1t; off = idx -  524288; }
    else                    { src = W2; dst = g_W2t; off = idx -  786432; }
    dst[off] = f2tf32(src[off]);
}

// ---------------- tf32 GEMM, cp.async double-buffered ----------------
// BM = MT*32, BN = 64, BK = 32, 256 threads = 8 warps in 2(M) x 4(N) layout.
// All inputs pre-rounded to tf32; raw 16B async copies, no cvt in the loop.
#define SA 36   // As row stride (32 + 4 pad), 144B = 16B multiple
#define SB 68   // Bs row stride (64 + 4 pad), 272B = 16B multiple

template<int MT, int K, bool OUT_TF32>
__device__ __forceinline__ void pgemm_core(const float* __restrict__ A,
                                           const float* __restrict__ W,
                                           const float* __restrict__ bias,
                                           float* __restrict__ Out,
                                           int N, int act,
                                           const float* __restrict__ rowmask,
                                           int row0, int col0)
{
    constexpr int BM  = MT * 32;
    constexpr int AIT = BM / 32;          // 16B A-chunks per thread: BM*8 chunks / 256 thr
    constexpr int NK  = K / 32;

    __shared__ __align__(16) float As[2][BM][SA];
    __shared__ __align__(16) float Bs[2][32][SB];

    const int tid    = threadIdx.x;
    const int lane   = tid & 31;
    const int wid    = tid >> 5;
    const int warp_m = wid & 1;
    const int warp_n = wid >> 1;
    const int lr = lane >> 2;
    const int lc = lane & 3;

    // copy coords: A tile BM x 32 floats -> BM*8 16B chunks; B tile 32 x 64 -> 512 chunks
    int am_[AIT];
#pragma unroll
    for (int it = 0; it < AIT; it++) am_[it] = (tid + it * 256) >> 3;
    const int aq  = tid & 7;
    const int bk_[2] = { (tid + 0) >> 4, (tid + 256) >> 4 };
    const int bq  = tid & 15;

    unsigned sA[2][AIT], sB[2][2];
#pragma unroll
    for (int bf = 0; bf < 2; bf++) {
#pragma unroll
        for (int it = 0; it < AIT; it++)
            sA[bf][it] = (unsigned)__cvta_generic_to_shared(&As[bf][am_[it]][aq * 4]);
#pragma unroll
        for (int it = 0; it < 2; it++)
            sB[bf][it] = (unsigned)__cvta_generic_to_shared(&Bs[bf][bk_[it]][bq * 4]);
    }

    // issue tile 0 into buffer 0
#pragma unroll
    for (int it = 0; it < AIT; it++)
        cp_async16(sA[0][it], &A[(size_t)(row0 + am_[it]) * K + aq * 4]);
#pragma unroll
    for (int it = 0; it < 2; it++)
        cp_async16(sB[0][it], &W[(size_t)bk_[it] * N + col0 + bq * 4]);
    CP_COMMIT();

    float acc[MT][2][4];
#pragma unroll
    for (int mt = 0; mt < MT; mt++)
#pragma unroll
        for (int nt = 0; nt < 2; nt++)
#pragma unroll
            for (int i = 0; i < 4; i++) acc[mt][nt][i] = 0.f;

    int buf = 0;
#pragma unroll 2
    for (int ki = 0; ki < NK; ki++) {
        if (ki + 1 < NK) {
            const int kt = (ki + 1) * 32;
#pragma unroll
            for (int it = 0; it < AIT; it++)
                cp_async16(sA[buf ^ 1][it], &A[(size_t)(row0 + am_[it]) * K + kt + aq * 4]);
#pragma unroll
            for (int it = 0; it < 2; it++)
                cp_async16(sB[buf ^ 1][it], &W[(size_t)(kt + bk_[it]) * N + col0 + bq * 4]);
            CP_COMMIT();
            CP_WAIT(1);
        } else {
            CP_WAIT(0);
        }
        __syncthreads();

#pragma unroll
        for (int ks = 0; ks < 4; ks++) {
            const int k0 = ks * 8;
            unsigned b0[2], b1[2];
#pragma unroll
            for (int nt = 0; nt < 2; nt++) {
                const float* pb = &Bs[buf][k0 + lc][warp_n * 16 + nt * 8 + lr];
                b0[nt] = __float_as_uint(pb[0]);
                b1[nt] = __float_as_uint(pb[4 * SB]);
            }
#pragma unroll
            for (int mt = 0; mt < MT; mt++) {
                const float* pa = &As[buf][warp_m * (BM / 2) + mt * 16 + lr][k0 + lc];
                unsigned a0 = __float_as_uint(pa[0]);
                unsigned a1 = __float_as_uint(pa[8 * SA]);
                unsigned a2 = __float_as_uint(pa[4]);
                unsigned a3 = __float_as_uint(pa[8 * SA + 4]);
#pragma unroll
                for (int nt = 0; nt < 2; nt++)
                    mma_tf32(acc[mt][nt][0], acc[mt][nt][1], acc[mt][nt][2], acc[mt][nt][3],
                             a0, a1, a2, a3, b0[nt], b1[nt]);
            }
        }
        __syncthreads();
        buf ^= 1;
    }

    // epilogue
#pragma unroll
    for (int mt = 0; mt < MT; mt++) {
#pragma unroll
        for (int nt = 0; nt < 2; nt++) {
            const int col = col0 + warp_n * 16 + nt * 8 + 2 * lc;
            const float bv0 = bias[col], bv1 = bias[col + 1];
#pragma unroll
            for (int h = 0; h < 2; h++) {
                const int row = row0 + warp_m * (BM / 2) + mt * 16 + lr + h * 8;
                const float rm = rowmask ? rowmask[row] : 1.f;
                float v0 = acc[mt][nt][2 * h + 0] + bv0;
                float v1 = acc[mt][nt][2 * h + 1] + bv1;
                if (act) { v0 = fmaxf(v0, 0.f); v1 = fmaxf(v1, 0.f); }
                v0 *= rm; v1 *= rm;
                if (OUT_TF32) { v0 = f2tf32(v0); v1 = f2tf32(v1); }
                Out[(size_t)row * N + col]     = v0;
                Out[(size_t)row * N + col + 1] = v1;
            }
        }
    }
}

template<int MT, int K, bool OUT_TF32>
__global__ __launch_bounds__(256)
void pgemm_kernel(int Aid, int Wid, const float* __restrict__ bias,
                  int Oid, int N, int act, const float* __restrict__ rowmask)
{
    pgemm_core<MT, K, OUT_TF32>(scratch_ptr(Aid), scratch_ptr(Wid), bias,
                                scratch_ptr(Oid), N, act, rowmask,
                                blockIdx.y * MT * 32, blockIdx.x * 64);
}

// fused Q/K/V projections: blockIdx.z selects weight set + destination
__global__ __launch_bounds__(256)
void qkv_kernel(const float* __restrict__ bq, const float* __restrict__ bk,
                const float* __restrict__ bv, const float* __restrict__ rowmask)
{
    const float* W; const float* b; float* Out;
    if (blockIdx.z == 0)      { W = g_Wqt; b = bq; Out = g_Q; }
    else if (blockIdx.z == 1) { W = g_Wkt; b = bk; Out = g_K; }
    else                      { W = g_Wvt; b = bv; Out = g_V; }
    pgemm_core<2, DXD, false>(g_Xt, W, b, Out, DXD, 0, rowmask,
                              blockIdx.y * 64, blockIdx.x * 64);
}

// ---------------- attention: float4, 4-way j-parallel, per-channel softmax ----------------
__global__ __launch_bounds__(256)
void attn_kernel(const float* __restrict__ e_add,
                 const float* __restrict__ e_mul,
                 const float* __restrict__ y_x_add,
                 const float* __restrict__ y_x_mul,
                 const float* __restrict__ node_mask)
{
    const int bi  = blockIdx.x;          // b*N + i
    const int b   = bi >> 8;
    const int tid = threadIdx.x;
    const int jg  = tid >> 6;            // 0..3
    const int c0  = (tid & 63) * 4;      // channel quad base

    __shared__ __align__(16) float sm_ee[NN];   // mask_i * mask_j
    __shared__ __align__(16) float sm_on[NN];   // 1/0 gate
    __shared__ __align__(16) float red_s[4][NN];
    __shared__ __align__(16) float red_a[4][NN];

    if (tid < NN) {
        const float mj = node_mask[b * NN + tid];
        const float mi = node_mask[b * NN + (bi & (NN - 1))];
        sm_ee[tid] = mi * mj;
        sm_on[tid] = (mj > 0.f) ? 1.f : 0.f;
    }
    __syncthreads();

    const float inv_sqrt_df = 0.1767766952966369f;

    float4 q = *(const float4*)&g_Q[(size_t)bi * DXD + c0];
    q.x *= inv_sqrt_df; q.y *= inv_sqrt_df; q.z *= inv_sqrt_df; q.w *= inv_sqrt_df;

    const float* __restrict__ pem = e_mul + (size_t)bi * NN * DXD + c0;
    const float* __restrict__ pea = e_add + (size_t)bi * NN * DXD + c0;
    const float* __restrict__ pk  = g_K   + (size_t)b  * NN * DXD + c0;
    const float* __restrict__ pv  = g_V   + (size_t)b  * NN * DXD + c0;

    float4 s   = make_float4(0.f, 0.f, 0.f, 0.f);
    float4 acc = make_float4(0.f, 0.f, 0.f, 0.f);

#pragma unroll 4
    for (int j = jg; j < NN; j += 4) {
        const float ee = sm_ee[j];
        const float on = sm_on[j];
        const size_t off = (size_t)j * DXD;
        const float4 em = *(const float4*)(pem + off);
        const float4 ea = *(const float4*)(pea + off);
        const float4 kk = *(const float4*)(pk  + off);
        const float4 vv = *(const float4*)(pv  + off);

        float y, p;
        y = fmaf(q.x * kk.x, fmaf(em.x, ee, 1.f), ea.x * ee);
        p = on * __expf(y);  s.x += p;  acc.x = fmaf(p, vv.x, acc.x);
        y = fmaf(q.y * kk.y, fmaf(em.y, ee, 1.f), ea.y * ee);
        p = on * __expf(y);  s.y += p;  acc.y = fmaf(p, vv.y, acc.y);
        y = fmaf(q.z * kk.z, fmaf(em.z, ee, 1.f), ea.z * ee);
        p = on * __expf(y);  s.z += p;  acc.z = fmaf(p, vv.z, acc.z);
        y = fmaf(q.w * kk.w, fmaf(em.w, ee, 1.f), ea.w * ee);
        p = on * __expf(y);  s.w += p;  acc.w = fmaf(p, vv.w, acc.w);
    }

    *(float4*)&red_s[jg][c0] = s;
    *(float4*)&red_a[jg][c0] = acc;
    __syncthreads();

    if (jg == 0) {
        float4 s0 = *(float4*)&red_s[0][c0];
        float4 s1 = *(float4*)&red_s[1][c0];
        float4 s2 = *(float4*)&red_s[2][c0];
        float4 s3 = *(float4*)&red_s[3][c0];
        float4 a0 = *(float4*)&red_a[0][c0];
        float4 a1 = *(float4*)&red_a[1][c0];
        float4 a2 = *(float4*)&red_a[2][c0];
        float4 a3 = *(float4*)&red_a[3][c0];

        const float4 ya = *(const float4*)&y_x_add[b * DXD + c0];
        const float4 ym = *(const float4*)&y_x_mul[b * DXD + c0];

        float4 o;   // tf32-rounded: g_att feeds the Wo GEMM only
        o.x = f2tf32(ya.x + (ym.x + 1.f) * ((a0.x + a1.x + a2.x + a3.x) / (s0.x + s1.x + s2.x + s3.x)));
        o.y = f2tf32(ya.y + (ym.y + 1.f) * ((a0.y + a1.y + a2.y + a3.y) / (s0.y + s1.y + s2.y + s3.y)));
        o.z = f2tf32(ya.z + (ym.z + 1.f) * ((a0.z + a1.z + a2.z + a3.z) / (s0.z + s1.z + s2.z + s3.z)));
        o.w = f2tf32(ya.w + (ym.w + 1.f) * ((a0.w + a1.w + a2.w + a3.w) / (s0.w + s1.w + s2.w + s3.w)));
        *(float4*)&g_att[(size_t)bi * DXD + c0] = o;
    }
}

// ---------------- single-pass layer norm over last dim (256) ----------------
// dual=1: also write a tf32-rounded copy to g_X1t
__global__ __launch_bounds__(256)
void ln_kernel(const float* __restrict__ Aext, int Aid,
               const float* __restrict__ Bext, int Bid,
               const float* __restrict__ g, const float* __restrict__ beta,
               float* __restrict__ Oext, int Oid, int dual)
{
    const float* A = Aext ? Aext : scratch_ptr(Aid);
    const float* B = Bext ? Bext : scratch_ptr(Bid);
    float* Out = Oext ? Oext : scratch_ptr(Oid);

    __shared__ float red[16];

    const int row = blockIdx.x;
    const int t   = threadIdx.x;

    const float x = A[(size_t)row * DXD + t] + B[(size_t)row * DXD + t];
    float sx = x, sxx = x * x;
#pragma unroll
    for (int o = 16; o; o >>= 1) {
        sx  += __shfl_xor_sync(0xffffffffu, sx,  o);
        sxx += __shfl_xor_sync(0xffffffffu, sxx, o);
    }
    if ((t & 31) == 0) { red[t >> 5] = sx; red[8 + (t >> 5)] = sxx; }
    __syncthreads();
    sx  = red[0] + red[1] + red[2]  + red[3]  + red[4]  + red[5]  + red[6]  + red[7];
    sxx = red[8] + red[9] + red[10] + red[11] + red[12] + red[13] + red[14] + red[15];

    const float mu  = sx * (1.f / DXD);
    const float var = sxx * (1.f / DXD) - mu * mu;
    const float v = (x - mu) * rsqrtf(var + EPSV) * g[t] + beta[t];
    Out[(size_t)row * DXD + t] = v;
    if (dual) g_X1t[(size_t)row * DXD + t] = f2tf32(v);
}

// ---------------- launch ----------------
extern "C" void kernel_launch(void* const* d_in, const int* in_sizes, int n_in,
                              void* d_out, int out_size)
{
    const float* X      = (const float*)d_in[0];
    const float* e_add  = (const float*)d_in[1];
    const float* e_mul  = (const float*)d_in[2];
    const float* yxa    = (const float*)d_in[3];
    const float* yxm    = (const float*)d_in[4];
    const float* nmask  = (const float*)d_in[5];
    const float* Wq     = (const float*)d_in[6];
    const float* bq     = (const float*)d_in[7];
    const float* Wk     = (const float*)d_in[8];
    const float* bk     = (const float*)d_in[9];
    const float* Wv     = (const float*)d_in[10];
    const float* bv     = (const float*)d_in[11];
    const float* Wo     = (const float*)d_in[12];
    const float* bo     = (const float*)d_in[13];
    const float* W1     = (const float*)d_in[14];
    const float* b1     = (const float*)d_in[15];
    const float* W2     = (const float*)d_in[16];
    const float* b2     = (const float*)d_in[17];
    const float* g1     = (const float*)d_in[18];
    const float* beta1  = (const float*)d_in[19];
    const float* g2     = (const float*)d_in[20];
    const float* b2ln   = (const float*)d_in[21];
    float* out          = (float*)d_out;

    // 0) round X + weights to tf32 (1,048,576 elements)
    prep_kernel<<<4096, 256>>>(X, Wq, Wk, Wv, Wo, W1, W2);

    // 1) fused QKV (cp.async tf32): 192 blocks
    qkv_kernel<<<dim3(DXD / 64, MROWS / 64, 3), 256>>>(bq, bk, bv, nmask);

    // 2) edge-modulated per-channel attention -> g_att (tf32-rounded)
    attn_kernel<<<MROWS, 256>>>(e_add, e_mul, yxa, yxm, nmask);

    // 3) output projection (masked): BM=32 -> 128 blocks
    pgemm_kernel<1, DXD, false><<<dim3(DXD / 64, MROWS / 32), 256>>>(3, 12, bo, 4, DXD, 0, nmask);

    // 4) LN1: X1 = LN(X + proj), dual store (fp32 + tf32)
    ln_kernel<<<MROWS, 256>>>(X, -1, nullptr, 4, g1, beta1, nullptr, 5, 1);

    // 5) FFN1: relu(X1t @ W1t + b1) -> ffn1 (tf32-rounded): 256 blocks
    pgemm_kernel<2, DXD, true><<<dim3(DFFD / 64, MROWS / 64), 256>>>(15, 13, b1, 6, DFFD, 1, nullptr);

    // 6) FFN2: ffn1 @ W2t + b2: 128 blocks, K=1024
    pgemm_kernel<1, DFFD, false><<<dim3(DXD / 64, MROWS / 32), 256>>>(6, 14, b2, 7, DXD, 0, nullptr);

    // 7) LN2 -> out
    ln_kernel<<<MROWS, 256>>>(nullptr, 5, nullptr, 7, g2, b2ln, out, -1, 0);
}